// round 12
// baseline (speedup 1.0000x reference)
#include <cuda_runtime.h>

#define N_NODES_C 100000
#define N_EDGES_C 300000
#define N_BATCH_C 50000
#define D_EMB     128
#define D_HID     64
#define N_HEADS   8
#define MAX_COMP  50000

typedef unsigned long long ull;

// ---------------- scratch ----------------
// zero-blob: [flag N][degN N][gate 8][nact,ncomp,total][pad]
__device__ int   g_zblob[2 * N_NODES_C + 16];
#define g_flag  (g_zblob)
#define g_degN  (g_zblob + N_NODES_C)
#define g_gate  ((float*)(g_zblob + 2 * N_NODES_C))
#define g_nact  (g_zblob[2 * N_NODES_C + 8])
#define g_ncomp (g_zblob[2 * N_NODES_C + 9])
#define g_total (g_zblob[2 * N_NODES_C + 10])

__device__ float g_edata [(size_t)N_EDGES_C * D_HID];
__device__ float g_logits[(size_t)N_EDGES_C * N_HEADS];
__device__ float g_nodec [(size_t)MAX_COMP * N_HEADS * D_HID];
__device__ int   g_cidx  [N_NODES_C];
__device__ int   g_degc  [MAX_COMP];
__device__ int   g_mult  [MAX_COMP];
__device__ int   g_rowptr[MAX_COMP];
__device__ int   g_cursor[MAX_COMP];
__device__ int   g_csr   [N_EDGES_C];
__device__ int   g_act   [N_EDGES_C];

// ---------------- f32x2 helpers ----------------
__device__ __forceinline__ ull pack2(float x) {
    ull r; asm("mov.b64 %0, {%1, %1};" : "=l"(r) : "f"(x)); return r;
}
__device__ __forceinline__ void fma2(ull& acc, ull a, ull b) {
    asm("fma.rn.f32x2 %0, %1, %2, %0;" : "+l"(acc) : "l"(a), "l"(b));
}
__device__ __forceinline__ void unpack2(ull v, float& lo, float& hi) {
    asm("mov.b64 {%0, %1}, %2;" : "=f"(lo), "=f"(hi) : "l"(v));
}

// =======================================================================
// K0a: flag + multiplicity count per node
extern "C" __global__ void k0a_flags(const int* __restrict__ bn, int B)
{
    int b = blockIdx.x * blockDim.x + threadIdx.x;
    if (b < B) atomicAdd(&g_flag[bn[b]], 1);
}

// K0c: compact active edges + per-NODE degree (needs only flags)
extern "C" __global__ void k0c_compact(const int* __restrict__ edst, int E)
{
    int e = blockIdx.x * blockDim.x + threadIdx.x;
    if (e >= E) return;
    int dst = edst[e];
    if (g_flag[dst] > 0) {
        int p = atomicAdd(&g_nact, 1);
        g_act[p] = e;
        atomicAdd(&g_degN[dst], 1);
    }
}

// K0bd: fused compaction: cidx, mult, compact deg, rowptr, cursor
extern "C" __global__ void k0bd_index(int N)
{
    int n = blockIdx.x * blockDim.x + threadIdx.x;
    if (n >= N) return;
    int m = g_flag[n];
    if (m > 0) {
        int c = atomicAdd(&g_ncomp, 1);
        g_cidx[n] = c;
        g_mult[c] = m;
        int d = g_degN[n];
        g_degc[c] = d;
        int s = atomicAdd(&g_total, d);
        g_rowptr[c] = s;
        g_cursor[c] = s;
    }
}

// K0e: fill CSR
extern "C" __global__ void k0e_fill(const int* __restrict__ edst)
{
    int i = blockIdx.x * blockDim.x + threadIdx.x;
    if (i >= g_nact) return;
    int e = g_act[i];
    int c = g_cidx[edst[e]];
    int pos = atomicAdd(&g_cursor[c], 1);
    g_csr[pos] = e;
}

// =======================================================================
// K1: edata GEMM. 12 warps x 16 edges (8 packed pairs). W k-split:
// phase A stages W_i (k<128, 32KB), phase B restages W_p. Accumulators
// persist in registers across phases. s tiles: 12*8*2KB = 192KB.
// =======================================================================
#define K1_WARPS 12
#define K1_TP    8
#define K1_T     (2 * K1_TP)
#define K1_TILE  (K1_WARPS * K1_T)       // 192 edges/block
#define K1_THREADS (K1_WARPS * 32)       // 384
#define K1_SMEM  ((32 * 64 * 4 + K1_WARPS * K1_TP * 512) * 4)  // 229376 B

extern "C" __global__ void __launch_bounds__(K1_THREADS, 1)
k1_edata(const int* __restrict__ mi, const float* __restrict__ feat,
         const float* __restrict__ Wi, const float* __restrict__ Wp)
{
    int cnt = g_nact;
    if (blockIdx.x * K1_TILE >= cnt) return;

    extern __shared__ float smem[];
    float* sW = smem;                         // [32 k4][64 d][4] = 32KB
    float* sS = smem + 32 * 64 * 4;           // [12][8tp][512]   = 192KB

    int tid = threadIdx.x;
    int warp = tid >> 5, lane = tid & 31;
    float* myS = sS + warp * (K1_TP * 512);
    long base = ((long)blockIdx.x * K1_WARPS + warp) * K1_T;

    // ---- stage W_i (k in [0,128)) ----
    for (int i = tid; i < 32 * 64; i += K1_THREADS) {
        int k4 = i >> 6, d = i & 63;
        *(float4*)(sW + (size_t)i * 4) = *(const float4*)(Wi + d * 128 + k4 * 4);
    }

    int eids[K1_T];
    #pragma unroll
    for (int t = 0; t < K1_T; t++) {
        long i = base + t;
        eids[t] = (i < cnt) ? g_act[i] : -1;
    }

    // ---- gather + build t-pair interleaved s tiles ----
    #pragma unroll 2
    for (int tp = 0; tp < K1_TP; tp++) {
        float4 si0 = make_float4(0.f,0.f,0.f,0.f), sp0 = si0;
        float4 si1 = si0, sp1 = si0;
        int e0 = eids[2*tp], e1 = eids[2*tp+1];
        if (e0 >= 0) {
            int4 idx = *(const int4*)(mi + (long)e0 * 4);
            float4 a = ((const float4*)(feat + (long)idx.x * 128))[lane];
            float4 b = ((const float4*)(feat + (long)idx.y * 128))[lane];
            float4 c = ((const float4*)(feat + (long)idx.z * 128))[lane];
            float4 d4 = ((const float4*)(feat + (long)idx.w * 128))[lane];
            si0.x = a.x + d4.x; si0.y = a.y + d4.y; si0.z = a.z + d4.z; si0.w = a.w + d4.w;
            sp0.x = b.x + c.x;  sp0.y = b.y + c.y;  sp0.z = b.z + c.z;  sp0.w = b.w + c.w;
        }
        if (e1 >= 0) {
            int4 idx = *(const int4*)(mi + (long)e1 * 4);
            float4 a = ((const float4*)(feat + (long)idx.x * 128))[lane];
            float4 b = ((const float4*)(feat + (long)idx.y * 128))[lane];
            float4 c = ((const float4*)(feat + (long)idx.z * 128))[lane];
            float4 d4 = ((const float4*)(feat + (long)idx.w * 128))[lane];
            si1.x = a.x + d4.x; si1.y = a.y + d4.y; si1.z = a.z + d4.z; si1.w = a.w + d4.w;
            sp1.x = b.x + c.x;  sp1.y = b.y + c.y;  sp1.z = b.z + c.z;  sp1.w = b.w + c.w;
        }
        float* bp = myS + tp * 512;
        *(float4*)(bp + (lane*4)*2)           = make_float4(si0.x, si1.x, si0.y, si1.y);
        *(float4*)(bp + (lane*4)*2 + 4)       = make_float4(si0.z, si1.z, si0.w, si1.w);
        *(float4*)(bp + (128+lane*4)*2)       = make_float4(sp0.x, sp1.x, sp0.y, sp1.y);
        *(float4*)(bp + (128+lane*4)*2 + 4)   = make_float4(sp0.z, sp1.z, sp0.w, sp1.w);
    }
    __syncthreads();   // W_i staged + all s tiles ready

    ull acc0[K1_TP], acc1[K1_TP];
    #pragma unroll
    for (int tp = 0; tp < K1_TP; tp++) { acc0[tp] = 0ull; acc1[tp] = 0ull; }

    // ---- phase A: k in [0,128) with W_i ----
    #pragma unroll 4
    for (int k4 = 0; k4 < 32; k4++) {
        float4 w0 = *(float4*)(sW + (size_t)(k4 * 64 + lane) * 4);
        float4 w1 = *(float4*)(sW + (size_t)(k4 * 64 + lane + 32) * 4);
        ull W0x = pack2(w0.x), W0y = pack2(w0.y), W0z = pack2(w0.z), W0w = pack2(w0.w);
        ull W1x = pack2(w1.x), W1y = pack2(w1.y), W1z = pack2(w1.z), W1w = pack2(w1.w);
        #pragma unroll
        for (int tp = 0; tp < K1_TP; tp++) {
            const float* sp2 = myS + tp * 512 + k4 * 8;
            ulonglong2 sa = *(const ulonglong2*)(sp2);
            ulonglong2 sb = *(const ulonglong2*)(sp2 + 4);
            fma2(acc0[tp], W0x, sa.x); fma2(acc0[tp], W0y, sa.y);
            fma2(acc0[tp], W0z, sb.x); fma2(acc0[tp], W0w, sb.y);
            fma2(acc1[tp], W1x, sa.x); fma2(acc1[tp], W1y, sa.y);
            fma2(acc1[tp], W1z, sb.x); fma2(acc1[tp], W1w, sb.y);
        }
    }

    // ---- restage W_p ----
    __syncthreads();
    for (int i = tid; i < 32 * 64; i += K1_THREADS) {
        int k4 = i >> 6, d = i & 63;
        *(float4*)(sW + (size_t)i * 4) = *(const float4*)(Wp + d * 128 + k4 * 4);
    }
    __syncthreads();

    // ---- phase B: k in [128,256) with W_p ----
    #pragma unroll 4
    for (int k4 = 0; k4 < 32; k4++) {
        float4 w0 = *(float4*)(sW + (size_t)(k4 * 64 + lane) * 4);
        float4 w1 = *(float4*)(sW + (size_t)(k4 * 64 + lane + 32) * 4);
        ull W0x = pack2(w0.x), W0y = pack2(w0.y), W0z = pack2(w0.z), W0w = pack2(w0.w);
        ull W1x = pack2(w1.x), W1y = pack2(w1.y), W1z = pack2(w1.z), W1w = pack2(w1.w);
        #pragma unroll
        for (int tp = 0; tp < K1_TP; tp++) {
            const float* sp2 = myS + tp * 512 + 256 + k4 * 8;
            ulonglong2 sa = *(const ulonglong2*)(sp2);
            ulonglong2 sb = *(const ulonglong2*)(sp2 + 4);
            fma2(acc0[tp], W0x, sa.x); fma2(acc0[tp], W0y, sa.y);
            fma2(acc0[tp], W0z, sb.x); fma2(acc0[tp], W0w, sb.y);
            fma2(acc1[tp], W1x, sa.x); fma2(acc1[tp], W1y, sa.y);
            fma2(acc1[tp], W1z, sb.x); fma2(acc1[tp], W1w, sb.y);
        }
    }

    #pragma unroll
    for (int tp = 0; tp < K1_TP; tp++) {
        float a0lo, a0hi, a1lo, a1hi;
        unpack2(acc0[tp], a0lo, a0hi);
        unpack2(acc1[tp], a1lo, a1hi);
        int e0 = eids[2*tp], e1 = eids[2*tp+1];
        if (e0 >= 0) {
            g_edata[(long)e0 * 64 + lane]      = a0lo;
            g_edata[(long)e0 * 64 + lane + 32] = a1lo;
        }
        if (e1 >= 0) {
            g_edata[(long)e1 * 64 + lane]      = a0hi;
            g_edata[(long)e1 * 64 + lane + 32] = a1hi;
        }
    }
}

// =======================================================================
// K2: ex = exp(lrelu(talking-heads logits)); store only (no atomics)
// =======================================================================
extern "C" __global__ void k2_logits(const float* __restrict__ attn,
                                     const float* __restrict__ Wth)
{
    __shared__ float sA[N_HEADS * 64];
    __shared__ float sT[N_HEADS * N_HEADS];
    int tid = threadIdx.x;
    for (int i = tid; i < N_HEADS * 64; i += 256) sA[i] = attn[i];
    if (tid < N_HEADS * N_HEADS) sT[tid] = Wth[tid];
    __syncthreads();

    int cnt = g_nact;
    int i = blockIdx.x * 256 + tid;
    if (i >= cnt) return;
    int e = g_act[i];

    const float* ed = g_edata + (long)e * 64;
    float t[N_HEADS];
    #pragma unroll
    for (int h = 0; h < N_HEADS; h++) t[h] = 0.f;
    #pragma unroll
    for (int d4 = 0; d4 < 16; d4++) {
        float4 v = *(const float4*)(ed + d4 * 4);
        #pragma unroll
        for (int h = 0; h < N_HEADS; h++) {
            const float* a = sA + h * 64 + d4 * 4;
            t[h] += v.x * a[0] + v.y * a[1] + v.z * a[2] + v.w * a[3];
        }
    }
    #pragma unroll
    for (int hp = 0; hp < N_HEADS; hp++) {
        float x = 0.f;
        #pragma unroll
        for (int h = 0; h < N_HEADS; h++) x += t[h] * sT[hp * 8 + h];
        x = (x > 0.f) ? x : 0.01f * x;
        g_logits[(long)e * 8 + hp] = __expf(x);
    }
}

// =======================================================================
// K4csr: warp per compact node, single pass (den + raw sum), normalize,
// write compact node_ft, fused gate epilogue.
// =======================================================================
extern "C" __global__ void k4_csr(const float* __restrict__ Wg)
{
    __shared__ float sG[N_HEADS];
    int tid = threadIdx.x;
    if (tid < N_HEADS) sG[tid] = 0.f;
    __syncthreads();

    int gw = (blockIdx.x * blockDim.x + tid) >> 5;
    int lane = tid & 31;
    int ncomp = g_ncomp;

    if (gw < ncomp) {
        int start = g_rowptr[gw];
        int deg   = g_degc[gw];

        float den = 0.f;
        float acc[16];
        #pragma unroll
        for (int k = 0; k < 16; k++) acc[k] = 0.f;

        for (int j = 0; j < deg; j++) {
            int e = g_csr[start + j];
            float ex = 0.f;
            if (lane < 8) ex = g_logits[(long)e * 8 + lane];
            den += ex;
            float e0 = g_edata[(long)e * 64 + lane];
            float e1 = g_edata[(long)e * 64 + lane + 32];
            #pragma unroll
            for (int h = 0; h < N_HEADS; h++) {
                float a = __shfl_sync(0xffffffffu, ex, h);
                acc[2*h]     += a * e0;
                acc[2*h + 1] += a * e1;
            }
        }

        float rden = (lane < 8 && den != 0.f) ? (1.0f / den) : 0.f;
        #pragma unroll
        for (int h = 0; h < N_HEADS; h++) {
            float r = __shfl_sync(0xffffffffu, rden, h);
            acc[2*h]     *= r;
            acc[2*h + 1] *= r;
        }

        float* nf = g_nodec + (long)gw * 512;
        #pragma unroll
        for (int h = 0; h < N_HEADS; h++) {
            nf[h * 64 + lane]      = acc[2*h];
            nf[h * 64 + 32 + lane] = acc[2*h + 1];
        }

        float wg0 = __ldg(Wg + lane);
        float wg1 = __ldg(Wg + lane + 32);
        float m = (float)g_mult[gw];
        #pragma unroll
        for (int h = 0; h < N_HEADS; h++) {
            float v = acc[2*h] * wg0 + acc[2*h + 1] * wg1;
            #pragma unroll
            for (int o = 16; o > 0; o >>= 1)
                v += __shfl_xor_sync(0xffffffffu, v, o);
            if (lane == 0) atomicAdd(&sG[h], m * v);
        }
    }

    __syncthreads();
    if (tid < N_HEADS) atomicAdd(&g_gate[tid], sG[tid]);
}

// =======================================================================
// K6: out = nodec[cidx[bn[b]]] * (gate[h]/B + b_gate)
// =======================================================================
extern "C" __global__ void k6_out(const int* __restrict__ bn,
                                  const float* __restrict__ bg,
                                  float* __restrict__ out, int B)
{
    long gid = (long)blockIdx.x * blockDim.x + threadIdx.x;
    if (gid >= (long)B * 128) return;
    int b = (int)(gid >> 7);
    int rem = ((int)gid & 127) << 2;
    int h = rem >> 6;
    float g = g_gate[h] * (1.0f / (float)B) + bg[0];
    int c = g_cidx[bn[b]];
    const float4 v = *(const float4*)(g_nodec + (long)c * 512 + rem);
    float4 o = make_float4(v.x * g, v.y * g, v.z * g, v.w * g);
    *(float4*)(out + (long)b * 512 + rem) = o;
}

// =======================================================================
extern "C" void kernel_launch(void* const* d_in, const int* in_sizes, int n_in,
                              void* d_out, int out_size)
{
    const int*   bn   = (const int*)  d_in[0];
    const int*   mi   = (const int*)  d_in[1];
    const int*   edst = (const int*)  d_in[2];
    const float* feat = (const float*)d_in[3];
    const float* Wi   = (const float*)d_in[4];
    const float* Wp   = (const float*)d_in[5];
    const float* attn = (const float*)d_in[6];
    const float* Wth  = (const float*)d_in[7];
    const float* Wg   = (const float*)d_in[8];
    const float* bg   = (const float*)d_in[9];

    int B = in_sizes[0];
    int E = in_sizes[2];

    void* p;
    cudaGetSymbolAddress(&p, g_zblob);
    cudaMemsetAsync(p, 0, sizeof(int) * (2 * N_NODES_C + 16));

    k0a_flags  <<<(B + 255) / 256, 256>>>(bn, B);
    k0c_compact<<<(E + 255) / 256, 256>>>(edst, E);
    k0bd_index <<<(N_NODES_C + 255) / 256, 256>>>(N_NODES_C);
    k0e_fill   <<<(E + 255) / 256, 256>>>(edst);

    cudaFuncSetAttribute(k1_edata, cudaFuncAttributeMaxDynamicSharedMemorySize, K1_SMEM);
    int blocks1 = (E + K1_TILE - 1) / K1_TILE;
    k1_edata<<<blocks1, K1_THREADS, K1_SMEM>>>(mi, feat, Wi, Wp);

    k2_logits<<<(E + 255) / 256, 256>>>(attn, Wth);

    long k4threads = (long)MAX_COMP * 32;
    k4_csr<<<(int)((k4threads + 255) / 256), 256>>>(Wg);

    long k6threads = (long)B * 128;
    k6_out<<<(int)((k6threads + 255) / 256), 256>>>(bn, bg, (float*)d_out, B);
}

// round 13
// speedup vs baseline: 1.0426x; 1.0426x over previous
#include <cuda_runtime.h>

#define N_NODES_C 100000
#define N_EDGES_C 300000
#define N_BATCH_C 50000
#define D_EMB     128
#define D_HID     64
#define N_HEADS   8
#define MAX_COMP  50000

typedef unsigned long long ull;

// ---------------- scratch ----------------
__device__ float g_edata [(size_t)N_EDGES_C * D_HID];
__device__ float g_nodec [(size_t)MAX_COMP * N_HEADS * D_HID];
__device__ float g_gate  [N_HEADS];
__device__ int   g_flag  [N_NODES_C];      // doubles as batch multiplicity
__device__ int   g_cidx  [N_NODES_C];
__device__ int   g_deg   [MAX_COMP];
__device__ int   g_mult  [MAX_COMP];
__device__ int   g_rowptr[MAX_COMP];
__device__ int   g_cursor[MAX_COMP];
__device__ int   g_csr   [N_EDGES_C];
__device__ int   g_act   [N_EDGES_C];
__device__ int   g_nact;
__device__ int   g_ncomp;
__device__ int   g_total;

// ---------------- f32x2 helpers ----------------
__device__ __forceinline__ ull pack2(float x) {
    ull r; asm("mov.b64 %0, {%1, %1};" : "=l"(r) : "f"(x)); return r;
}
__device__ __forceinline__ void fma2(ull& acc, ull a, ull b) {
    asm("fma.rn.f32x2 %0, %1, %2, %0;" : "+l"(acc) : "l"(a), "l"(b));
}
__device__ __forceinline__ void unpack2(ull v, float& lo, float& hi) {
    asm("mov.b64 {%0, %1}, %2;" : "=f"(lo), "=f"(hi) : "l"(v));
}

// =======================================================================
// K0a: flag + multiplicity count per node
extern "C" __global__ void k0a_flags(const int* __restrict__ bn, int B)
{
    int b = blockIdx.x * blockDim.x + threadIdx.x;
    if (b < B) atomicAdd(&g_flag[bn[b]], 1);
}

// K0b: compact index + copy multiplicity
extern "C" __global__ void k0b_cidx(int N)
{
    int n = blockIdx.x * blockDim.x + threadIdx.x;
    if (n >= N) return;
    int m = g_flag[n];
    if (m > 0) {
        int c = atomicAdd(&g_ncomp, 1);
        g_cidx[n] = c;
        g_mult[c] = m;
    }
}

// K0c: compact active edges + degree
extern "C" __global__ void k0c_compact(const int* __restrict__ edst, int E)
{
    int e = blockIdx.x * blockDim.x + threadIdx.x;
    if (e >= E) return;
    int dst = edst[e];
    if (g_flag[dst] > 0) {
        int p = atomicAdd(&g_nact, 1);
        g_act[p] = e;
        atomicAdd(&g_deg[g_cidx[dst]], 1);
    }
}

// K0d: rowptr via atomic offset allocation
extern "C" __global__ void k0d_rowptr()
{
    int c = blockIdx.x * blockDim.x + threadIdx.x;
    if (c >= g_ncomp) return;
    int s = atomicAdd(&g_total, g_deg[c]);
    g_rowptr[c] = s;
    g_cursor[c] = s;
}

// K0e: fill CSR
extern "C" __global__ void k0e_fill(const int* __restrict__ edst)
{
    int i = blockIdx.x * blockDim.x + threadIdx.x;
    if (i >= g_nact) return;
    int e = g_act[i];
    int c = g_cidx[edst[e]];
    int pos = atomicAdd(&g_cursor[c], 1);
    g_csr[pos] = e;
}

// =======================================================================
// K1: edata GEMM. 12 warps x 16 edges (8 packed pairs). W k-split:
// phase A stages W_i (k<128, 32KB), phase B restages W_p.
// =======================================================================
#define K1_WARPS 12
#define K1_TP    8
#define K1_T     (2 * K1_TP)
#define K1_TILE  (K1_WARPS * K1_T)       // 192 edges/block
#define K1_THREADS (K1_WARPS * 32)       // 384
#define K1_SMEM  ((32 * 64 * 4 + K1_WARPS * K1_TP * 512) * 4)  // 229376 B

extern "C" __global__ void __launch_bounds__(K1_THREADS, 1)
k1_edata(const int* __restrict__ mi, const float* __restrict__ feat,
         const float* __restrict__ Wi, const float* __restrict__ Wp)
{
    int cnt = g_nact;
    if (blockIdx.x * K1_TILE >= cnt) return;

    extern __shared__ float smem[];
    float* sW = smem;                         // [32 k4][64 d][4] = 32KB
    float* sS = smem + 32 * 64 * 4;           // [12][8tp][512]   = 192KB

    int tid = threadIdx.x;
    int warp = tid >> 5, lane = tid & 31;
    float* myS = sS + warp * (K1_TP * 512);
    long base = ((long)blockIdx.x * K1_WARPS + warp) * K1_T;

    for (int i = tid; i < 32 * 64; i += K1_THREADS) {
        int k4 = i >> 6, d = i & 63;
        *(float4*)(sW + (size_t)i * 4) = *(const float4*)(Wi + d * 128 + k4 * 4);
    }

    int eids[K1_T];
    #pragma unroll
    for (int t = 0; t < K1_T; t++) {
        long i = base + t;
        eids[t] = (i < cnt) ? g_act[i] : -1;
    }

    #pragma unroll 2
    for (int tp = 0; tp < K1_TP; tp++) {
        float4 si0 = make_float4(0.f,0.f,0.f,0.f), sp0 = si0;
        float4 si1 = si0, sp1 = si0;
        int e0 = eids[2*tp], e1 = eids[2*tp+1];
        if (e0 >= 0) {
            int4 idx = *(const int4*)(mi + (long)e0 * 4);
            float4 a = ((const float4*)(feat + (long)idx.x * 128))[lane];
            float4 b = ((const float4*)(feat + (long)idx.y * 128))[lane];
            float4 c = ((const float4*)(feat + (long)idx.z * 128))[lane];
            float4 d4 = ((const float4*)(feat + (long)idx.w * 128))[lane];
            si0.x = a.x + d4.x; si0.y = a.y + d4.y; si0.z = a.z + d4.z; si0.w = a.w + d4.w;
            sp0.x = b.x + c.x;  sp0.y = b.y + c.y;  sp0.z = b.z + c.z;  sp0.w = b.w + c.w;
        }
        if (e1 >= 0) {
            int4 idx = *(const int4*)(mi + (long)e1 * 4);
            float4 a = ((const float4*)(feat + (long)idx.x * 128))[lane];
            float4 b = ((const float4*)(feat + (long)idx.y * 128))[lane];
            float4 c = ((const float4*)(feat + (long)idx.z * 128))[lane];
            float4 d4 = ((const float4*)(feat + (long)idx.w * 128))[lane];
            si1.x = a.x + d4.x; si1.y = a.y + d4.y; si1.z = a.z + d4.z; si1.w = a.w + d4.w;
            sp1.x = b.x + c.x;  sp1.y = b.y + c.y;  sp1.z = b.z + c.z;  sp1.w = b.w + c.w;
        }
        float* bp = myS + tp * 512;
        *(float4*)(bp + (lane*4)*2)           = make_float4(si0.x, si1.x, si0.y, si1.y);
        *(float4*)(bp + (lane*4)*2 + 4)       = make_float4(si0.z, si1.z, si0.w, si1.w);
        *(float4*)(bp + (128+lane*4)*2)       = make_float4(sp0.x, sp1.x, sp0.y, sp1.y);
        *(float4*)(bp + (128+lane*4)*2 + 4)   = make_float4(sp0.z, sp1.z, sp0.w, sp1.w);
    }
    __syncthreads();

    ull acc0[K1_TP], acc1[K1_TP];
    #pragma unroll
    for (int tp = 0; tp < K1_TP; tp++) { acc0[tp] = 0ull; acc1[tp] = 0ull; }

    #pragma unroll 4
    for (int k4 = 0; k4 < 32; k4++) {
        float4 w0 = *(float4*)(sW + (size_t)(k4 * 64 + lane) * 4);
        float4 w1 = *(float4*)(sW + (size_t)(k4 * 64 + lane + 32) * 4);
        ull W0x = pack2(w0.x), W0y = pack2(w0.y), W0z = pack2(w0.z), W0w = pack2(w0.w);
        ull W1x = pack2(w1.x), W1y = pack2(w1.y), W1z = pack2(w1.z), W1w = pack2(w1.w);
        #pragma unroll
        for (int tp = 0; tp < K1_TP; tp++) {
            const float* sp2 = myS + tp * 512 + k4 * 8;
            ulonglong2 sa = *(const ulonglong2*)(sp2);
            ulonglong2 sb = *(const ulonglong2*)(sp2 + 4);
            fma2(acc0[tp], W0x, sa.x); fma2(acc0[tp], W0y, sa.y);
            fma2(acc0[tp], W0z, sb.x); fma2(acc0[tp], W0w, sb.y);
            fma2(acc1[tp], W1x, sa.x); fma2(acc1[tp], W1y, sa.y);
            fma2(acc1[tp], W1z, sb.x); fma2(acc1[tp], W1w, sb.y);
        }
    }

    __syncthreads();
    for (int i = tid; i < 32 * 64; i += K1_THREADS) {
        int k4 = i >> 6, d = i & 63;
        *(float4*)(sW + (size_t)i * 4) = *(const float4*)(Wp + d * 128 + k4 * 4);
    }
    __syncthreads();

    #pragma unroll 4
    for (int k4 = 0; k4 < 32; k4++) {
        float4 w0 = *(float4*)(sW + (size_t)(k4 * 64 + lane) * 4);
        float4 w1 = *(float4*)(sW + (size_t)(k4 * 64 + lane + 32) * 4);
        ull W0x = pack2(w0.x), W0y = pack2(w0.y), W0z = pack2(w0.z), W0w = pack2(w0.w);
        ull W1x = pack2(w1.x), W1y = pack2(w1.y), W1z = pack2(w1.z), W1w = pack2(w1.w);
        #pragma unroll
        for (int tp = 0; tp < K1_TP; tp++) {
            const float* sp2 = myS + tp * 512 + 256 + k4 * 8;
            ulonglong2 sa = *(const ulonglong2*)(sp2);
            ulonglong2 sb = *(const ulonglong2*)(sp2 + 4);
            fma2(acc0[tp], W0x, sa.x); fma2(acc0[tp], W0y, sa.y);
            fma2(acc0[tp], W0z, sb.x); fma2(acc0[tp], W0w, sb.y);
            fma2(acc1[tp], W1x, sa.x); fma2(acc1[tp], W1y, sa.y);
            fma2(acc1[tp], W1z, sb.x); fma2(acc1[tp], W1w, sb.y);
        }
    }

    #pragma unroll
    for (int tp = 0; tp < K1_TP; tp++) {
        float a0lo, a0hi, a1lo, a1hi;
        unpack2(acc0[tp], a0lo, a0hi);
        unpack2(acc1[tp], a1lo, a1hi);
        int e0 = eids[2*tp], e1 = eids[2*tp+1];
        if (e0 >= 0) {
            g_edata[(long)e0 * 64 + lane]      = a0lo;
            g_edata[(long)e0 * 64 + lane + 32] = a1lo;
        }
        if (e1 >= 0) {
            g_edata[(long)e1 * 64 + lane]      = a0hi;
            g_edata[(long)e1 * 64 + lane + 32] = a1hi;
        }
    }
}

// =======================================================================
// K4csr: warp per compact node. For each edge: compute logits+exp INLINE
// from the edata row (attn/Wth hoisted to registers), accumulate den and
// raw weighted sum in one pass, normalize, write nodec, fused gate.
// =======================================================================
extern "C" __global__ void k4_csr(const float* __restrict__ attn,
                                  const float* __restrict__ Wth,
                                  const float* __restrict__ Wg)
{
    __shared__ float sG[N_HEADS];
    int tid = threadIdx.x;
    if (tid < N_HEADS) sG[tid] = 0.f;
    __syncthreads();

    int gw = (blockIdx.x * blockDim.x + tid) >> 5;
    int lane = tid & 31;
    int ncomp = g_ncomp;

    if (gw < ncomp) {
        int start = g_rowptr[gw];
        int deg   = g_deg[gw];

        // hoisted edge-invariant weights
        float aA0[N_HEADS], aA1[N_HEADS];
        #pragma unroll
        for (int h = 0; h < N_HEADS; h++) {
            aA0[h] = __ldg(attn + h * 64 + lane);
            aA1[h] = __ldg(attn + h * 64 + 32 + lane);
        }
        float wth[N_HEADS];
        #pragma unroll
        for (int h = 0; h < N_HEADS; h++)
            wth[h] = (lane < 8) ? __ldg(Wth + lane * 8 + h) : 0.f;

        float den = 0.f;
        float acc[16];
        #pragma unroll
        for (int k = 0; k < 16; k++) acc[k] = 0.f;

        for (int j = 0; j < deg; j++) {
            int e = g_csr[start + j];
            float e0 = g_edata[(long)e * 64 + lane];
            float e1 = g_edata[(long)e * 64 + lane + 32];

            // t[h] = edata . attn[h] (full 64-dim via warp butterfly)
            float t[N_HEADS];
            #pragma unroll
            for (int h = 0; h < N_HEADS; h++) {
                float v = e0 * aA0[h] + e1 * aA1[h];
                #pragma unroll
                for (int o = 16; o > 0; o >>= 1)
                    v += __shfl_xor_sync(0xffffffffu, v, o);
                t[h] = v;
            }
            // lanes 0-7: head hp=lane: talking-heads + lrelu + exp
            float ex = 0.f;
            if (lane < 8) {
                float x = 0.f;
                #pragma unroll
                for (int h = 0; h < N_HEADS; h++) x += t[h] * wth[h];
                x = (x > 0.f) ? x : 0.01f * x;
                ex = __expf(x);
            }
            den += ex;
            #pragma unroll
            for (int h = 0; h < N_HEADS; h++) {
                float a = __shfl_sync(0xffffffffu, ex, h);
                acc[2*h]     += a * e0;
                acc[2*h + 1] += a * e1;
            }
        }

        float rden = (lane < 8 && den != 0.f) ? (1.0f / den) : 0.f;
        #pragma unroll
        for (int h = 0; h < N_HEADS; h++) {
            float r = __shfl_sync(0xffffffffu, rden, h);
            acc[2*h]     *= r;
            acc[2*h + 1] *= r;
        }

        float* nf = g_nodec + (long)gw * 512;
        #pragma unroll
        for (int h = 0; h < N_HEADS; h++) {
            nf[h * 64 + lane]      = acc[2*h];
            nf[h * 64 + 32 + lane] = acc[2*h + 1];
        }

        float wg0 = __ldg(Wg + lane);
        float wg1 = __ldg(Wg + lane + 32);
        float m = (float)g_mult[gw];
        #pragma unroll
        for (int h = 0; h < N_HEADS; h++) {
            float v = acc[2*h] * wg0 + acc[2*h + 1] * wg1;
            #pragma unroll
            for (int o = 16; o > 0; o >>= 1)
                v += __shfl_xor_sync(0xffffffffu, v, o);
            if (lane == 0) atomicAdd(&sG[h], m * v);
        }
    }

    __syncthreads();
    if (tid < N_HEADS) atomicAdd(&g_gate[tid], sG[tid]);
}

// =======================================================================
// K6: out = nodec[cidx[bn[b]]] * (gate[h]/B + b_gate)
// =======================================================================
extern "C" __global__ void k6_out(const int* __restrict__ bn,
                                  const float* __restrict__ bg,
                                  float* __restrict__ out, int B)
{
    long gid = (long)blockIdx.x * blockDim.x + threadIdx.x;
    if (gid >= (long)B * 128) return;
    int b = (int)(gid >> 7);
    int rem = ((int)gid & 127) << 2;
    int h = rem >> 6;
    float g = g_gate[h] * (1.0f / (float)B) + bg[0];
    int c = g_cidx[bn[b]];
    const float4 v = *(const float4*)(g_nodec + (long)c * 512 + rem);
    float4 o = make_float4(v.x * g, v.y * g, v.z * g, v.w * g);
    *(float4*)(out + (long)b * 512 + rem) = o;
}

// =======================================================================
extern "C" void kernel_launch(void* const* d_in, const int* in_sizes, int n_in,
                              void* d_out, int out_size)
{
    const int*   bn   = (const int*)  d_in[0];
    const int*   mi   = (const int*)  d_in[1];
    const int*   edst = (const int*)  d_in[2];
    const float* feat = (const float*)d_in[3];
    const float* Wi   = (const float*)d_in[4];
    const float* Wp   = (const float*)d_in[5];
    const float* attn = (const float*)d_in[6];
    const float* Wth  = (const float*)d_in[7];
    const float* Wg   = (const float*)d_in[8];
    const float* bg   = (const float*)d_in[9];

    int B = in_sizes[0];
    int E = in_sizes[2];

    void* p;
    cudaGetSymbolAddress(&p, g_gate);
    cudaMemsetAsync(p, 0, sizeof(float) * N_HEADS);
    cudaGetSymbolAddress(&p, g_flag);
    cudaMemsetAsync(p, 0, sizeof(int) * N_NODES_C);
    cudaGetSymbolAddress(&p, g_deg);
    cudaMemsetAsync(p, 0, sizeof(int) * MAX_COMP);
    cudaGetSymbolAddress(&p, g_nact);
    cudaMemsetAsync(p, 0, sizeof(int));
    cudaGetSymbolAddress(&p, g_ncomp);
    cudaMemsetAsync(p, 0, sizeof(int));
    cudaGetSymbolAddress(&p, g_total);
    cudaMemsetAsync(p, 0, sizeof(int));

    k0a_flags  <<<(B + 255) / 256, 256>>>(bn, B);
    k0b_cidx   <<<(N_NODES_C + 255) / 256, 256>>>(N_NODES_C);
    k0c_compact<<<(E + 255) / 256, 256>>>(edst, E);
    k0d_rowptr <<<(MAX_COMP + 255) / 256, 256>>>();
    k0e_fill   <<<(E + 255) / 256, 256>>>(edst);

    cudaFuncSetAttribute(k1_edata, cudaFuncAttributeMaxDynamicSharedMemorySize, K1_SMEM);
    int blocks1 = (E + K1_TILE - 1) / K1_TILE;
    k1_edata<<<blocks1, K1_THREADS, K1_SMEM>>>(mi, feat, Wi, Wp);

    long k4threads = (long)MAX_COMP * 32;
    k4_csr<<<(int)((k4threads + 255) / 256), 256>>>(attn, Wth, Wg);

    long k6threads = (long)B * 128;
    k6_out<<<(int)((k6threads + 255) / 256), 256>>>(bn, bg, (float*)d_out, B);
}

// round 14
// speedup vs baseline: 1.0502x; 1.0073x over previous
#include <cuda_runtime.h>

#define N_NODES_C 100000
#define N_EDGES_C 300000
#define N_BATCH_C 50000
#define D_EMB     128
#define D_HID     64
#define N_HEADS   8
#define MAX_COMP  50000

typedef unsigned long long ull;

// ---------------- scratch ----------------
__device__ float g_edata [(size_t)N_EDGES_C * D_HID];
__device__ float g_nodec [(size_t)MAX_COMP * N_HEADS * D_HID];
__device__ float g_gate  [N_HEADS];
__device__ int   g_flag  [N_NODES_C];      // doubles as batch multiplicity
__device__ int   g_cidx  [N_NODES_C];
__device__ int   g_deg   [MAX_COMP];
__device__ int   g_mult  [MAX_COMP];
__device__ int   g_rowptr[MAX_COMP];
__device__ int   g_cursor[MAX_COMP];
__device__ int   g_csr   [N_EDGES_C];
__device__ int   g_act   [N_EDGES_C];
__device__ int   g_nact;
__device__ int   g_ncomp;
__device__ int   g_total;

// ---------------- f32x2 helpers ----------------
__device__ __forceinline__ ull pack2(float x) {
    ull r; asm("mov.b64 %0, {%1, %1};" : "=l"(r) : "f"(x)); return r;
}
__device__ __forceinline__ void fma2(ull& acc, ull a, ull b) {
    asm("fma.rn.f32x2 %0, %1, %2, %0;" : "+l"(acc) : "l"(a), "l"(b));
}
__device__ __forceinline__ void unpack2(ull v, float& lo, float& hi) {
    asm("mov.b64 {%0, %1}, %2;" : "=f"(lo), "=f"(hi) : "l"(v));
}

// =======================================================================
// K0a: flag + multiplicity count per node
extern "C" __global__ void k0a_flags(const int* __restrict__ bn, int B)
{
    int b = blockIdx.x * blockDim.x + threadIdx.x;
    if (b < B) atomicAdd(&g_flag[bn[b]], 1);
}

// K0b: compact index + copy multiplicity
extern "C" __global__ void k0b_cidx(int N)
{
    int n = blockIdx.x * blockDim.x + threadIdx.x;
    if (n >= N) return;
    int m = g_flag[n];
    if (m > 0) {
        int c = atomicAdd(&g_ncomp, 1);
        g_cidx[n] = c;
        g_mult[c] = m;
    }
}

// K0c: compact active edges + degree
extern "C" __global__ void k0c_compact(const int* __restrict__ edst, int E)
{
    int e = blockIdx.x * blockDim.x + threadIdx.x;
    if (e >= E) return;
    int dst = edst[e];
    if (g_flag[dst] > 0) {
        int p = atomicAdd(&g_nact, 1);
        g_act[p] = e;
        atomicAdd(&g_deg[g_cidx[dst]], 1);
    }
}

// K0d: rowptr via atomic offset allocation
extern "C" __global__ void k0d_rowptr()
{
    int c = blockIdx.x * blockDim.x + threadIdx.x;
    if (c >= g_ncomp) return;
    int s = atomicAdd(&g_total, g_deg[c]);
    g_rowptr[c] = s;
    g_cursor[c] = s;
}

// K0e: fill CSR
extern "C" __global__ void k0e_fill(const int* __restrict__ edst)
{
    int i = blockIdx.x * blockDim.x + threadIdx.x;
    if (i >= g_nact) return;
    int e = g_act[i];
    int c = g_cidx[edst[e]];
    int pos = atomicAdd(&g_cursor[c], 1);
    g_csr[pos] = e;
}

// =======================================================================
// K1: edata GEMM. 8 warps x 8 edges (4 packed pairs), 2 CTAs/SM so one
// CTA's compute overlaps the other's gather. W k-split (32KB resident).
// smem/CTA = 32KB W + 8*4*2KB s = 96KB -> 2 CTAs in 227KB.
// =======================================================================
#define K1_WARPS 8
#define K1_TP    4
#define K1_T     (2 * K1_TP)
#define K1_TILE  (K1_WARPS * K1_T)       // 64 edges/block
#define K1_THREADS (K1_WARPS * 32)       // 256
#define K1_SMEM  ((32 * 64 * 4 + K1_WARPS * K1_TP * 512) * 4)  // 98304 B

extern "C" __global__ void __launch_bounds__(K1_THREADS, 2)
k1_edata(const int* __restrict__ mi, const float* __restrict__ feat,
         const float* __restrict__ Wi, const float* __restrict__ Wp)
{
    int cnt = g_nact;
    if (blockIdx.x * K1_TILE >= cnt) return;

    extern __shared__ float smem[];
    float* sW = smem;                         // [32 k4][64 d][4] = 32KB
    float* sS = smem + 32 * 64 * 4;           // [8][4tp][512]    = 64KB

    int tid = threadIdx.x;
    int warp = tid >> 5, lane = tid & 31;
    float* myS = sS + warp * (K1_TP * 512);
    long base = ((long)blockIdx.x * K1_WARPS + warp) * K1_T;

    // ---- stage W_i (k in [0,128)) ----
    for (int i = tid; i < 32 * 64; i += K1_THREADS) {
        int k4 = i >> 6, d = i & 63;
        *(float4*)(sW + (size_t)i * 4) = *(const float4*)(Wi + d * 128 + k4 * 4);
    }

    int eids[K1_T];
    #pragma unroll
    for (int t = 0; t < K1_T; t++) {
        long i = base + t;
        eids[t] = (i < cnt) ? g_act[i] : -1;
    }

    // ---- gather + build t-pair interleaved s tiles ----
    #pragma unroll 2
    for (int tp = 0; tp < K1_TP; tp++) {
        float4 si0 = make_float4(0.f,0.f,0.f,0.f), sp0 = si0;
        float4 si1 = si0, sp1 = si0;
        int e0 = eids[2*tp], e1 = eids[2*tp+1];
        if (e0 >= 0) {
            int4 idx = *(const int4*)(mi + (long)e0 * 4);
            float4 a = ((const float4*)(feat + (long)idx.x * 128))[lane];
            float4 b = ((const float4*)(feat + (long)idx.y * 128))[lane];
            float4 c = ((const float4*)(feat + (long)idx.z * 128))[lane];
            float4 d4 = ((const float4*)(feat + (long)idx.w * 128))[lane];
            si0.x = a.x + d4.x; si0.y = a.y + d4.y; si0.z = a.z + d4.z; si0.w = a.w + d4.w;
            sp0.x = b.x + c.x;  sp0.y = b.y + c.y;  sp0.z = b.z + c.z;  sp0.w = b.w + c.w;
        }
        if (e1 >= 0) {
            int4 idx = *(const int4*)(mi + (long)e1 * 4);
            float4 a = ((const float4*)(feat + (long)idx.x * 128))[lane];
            float4 b = ((const float4*)(feat + (long)idx.y * 128))[lane];
            float4 c = ((const float4*)(feat + (long)idx.z * 128))[lane];
            float4 d4 = ((const float4*)(feat + (long)idx.w * 128))[lane];
            si1.x = a.x + d4.x; si1.y = a.y + d4.y; si1.z = a.z + d4.z; si1.w = a.w + d4.w;
            sp1.x = b.x + c.x;  sp1.y = b.y + c.y;  sp1.z = b.z + c.z;  sp1.w = b.w + c.w;
        }
        float* bp = myS + tp * 512;
        *(float4*)(bp + (lane*4)*2)           = make_float4(si0.x, si1.x, si0.y, si1.y);
        *(float4*)(bp + (lane*4)*2 + 4)       = make_float4(si0.z, si1.z, si0.w, si1.w);
        *(float4*)(bp + (128+lane*4)*2)       = make_float4(sp0.x, sp1.x, sp0.y, sp1.y);
        *(float4*)(bp + (128+lane*4)*2 + 4)   = make_float4(sp0.z, sp1.z, sp0.w, sp1.w);
    }
    __syncthreads();   // W_i staged + s tiles ready

    ull acc0[K1_TP], acc1[K1_TP];
    #pragma unroll
    for (int tp = 0; tp < K1_TP; tp++) { acc0[tp] = 0ull; acc1[tp] = 0ull; }

    // ---- phase A: k in [0,128) with W_i ----
    #pragma unroll 4
    for (int k4 = 0; k4 < 32; k4++) {
        float4 w0 = *(float4*)(sW + (size_t)(k4 * 64 + lane) * 4);
        float4 w1 = *(float4*)(sW + (size_t)(k4 * 64 + lane + 32) * 4);
        ull W0x = pack2(w0.x), W0y = pack2(w0.y), W0z = pack2(w0.z), W0w = pack2(w0.w);
        ull W1x = pack2(w1.x), W1y = pack2(w1.y), W1z = pack2(w1.z), W1w = pack2(w1.w);
        #pragma unroll
        for (int tp = 0; tp < K1_TP; tp++) {
            const float* sp2 = myS + tp * 512 + k4 * 8;
            ulonglong2 sa = *(const ulonglong2*)(sp2);
            ulonglong2 sb = *(const ulonglong2*)(sp2 + 4);
            fma2(acc0[tp], W0x, sa.x); fma2(acc0[tp], W0y, sa.y);
            fma2(acc0[tp], W0z, sb.x); fma2(acc0[tp], W0w, sb.y);
            fma2(acc1[tp], W1x, sa.x); fma2(acc1[tp], W1y, sa.y);
            fma2(acc1[tp], W1z, sb.x); fma2(acc1[tp], W1w, sb.y);
        }
    }

    // ---- restage W_p ----
    __syncthreads();
    for (int i = tid; i < 32 * 64; i += K1_THREADS) {
        int k4 = i >> 6, d = i & 63;
        *(float4*)(sW + (size_t)i * 4) = *(const float4*)(Wp + d * 128 + k4 * 4);
    }
    __syncthreads();

    // ---- phase B: k in [128,256) with W_p ----
    #pragma unroll 4
    for (int k4 = 0; k4 < 32; k4++) {
        float4 w0 = *(float4*)(sW + (size_t)(k4 * 64 + lane) * 4);
        float4 w1 = *(float4*)(sW + (size_t)(k4 * 64 + lane + 32) * 4);
        ull W0x = pack2(w0.x), W0y = pack2(w0.y), W0z = pack2(w0.z), W0w = pack2(w0.w);
        ull W1x = pack2(w1.x), W1y = pack2(w1.y), W1z = pack2(w1.z), W1w = pack2(w1.w);
        #pragma unroll
        for (int tp = 0; tp < K1_TP; tp++) {
            const float* sp2 = myS + tp * 512 + 256 + k4 * 8;
            ulonglong2 sa = *(const ulonglong2*)(sp2);
            ulonglong2 sb = *(const ulonglong2*)(sp2 + 4);
            fma2(acc0[tp], W0x, sa.x); fma2(acc0[tp], W0y, sa.y);
            fma2(acc0[tp], W0z, sb.x); fma2(acc0[tp], W0w, sb.y);
            fma2(acc1[tp], W1x, sa.x); fma2(acc1[tp], W1y, sa.y);
            fma2(acc1[tp], W1z, sb.x); fma2(acc1[tp], W1w, sb.y);
        }
    }

    #pragma unroll
    for (int tp = 0; tp < K1_TP; tp++) {
        float a0lo, a0hi, a1lo, a1hi;
        unpack2(acc0[tp], a0lo, a0hi);
        unpack2(acc1[tp], a1lo, a1hi);
        int e0 = eids[2*tp], e1 = eids[2*tp+1];
        if (e0 >= 0) {
            g_edata[(long)e0 * 64 + lane]      = a0lo;
            g_edata[(long)e0 * 64 + lane + 32] = a1lo;
        }
        if (e1 >= 0) {
            g_edata[(long)e1 * 64 + lane]      = a0hi;
            g_edata[(long)e1 * 64 + lane + 32] = a1hi;
        }
    }
}

// =======================================================================
// K4csr: warp per compact node; inline logits+exp from edata row,
// single-pass den + raw sum, normalize, write nodec, fused gate.
// =======================================================================
extern "C" __global__ void k4_csr(const float* __restrict__ attn,
                                  const float* __restrict__ Wth,
                                  const float* __restrict__ Wg)
{
    __shared__ float sG[N_HEADS];
    int tid = threadIdx.x;
    if (tid < N_HEADS) sG[tid] = 0.f;
    __syncthreads();

    int gw = (blockIdx.x * blockDim.x + tid) >> 5;
    int lane = tid & 31;
    int ncomp = g_ncomp;

    if (gw < ncomp) {
        int start = g_rowptr[gw];
        int deg   = g_deg[gw];

        float aA0[N_HEADS], aA1[N_HEADS];
        #pragma unroll
        for (int h = 0; h < N_HEADS; h++) {
            aA0[h] = __ldg(attn + h * 64 + lane);
            aA1[h] = __ldg(attn + h * 64 + 32 + lane);
        }
        float wth[N_HEADS];
        #pragma unroll
        for (int h = 0; h < N_HEADS; h++)
            wth[h] = (lane < 8) ? __ldg(Wth + lane * 8 + h) : 0.f;

        float den = 0.f;
        float acc[16];
        #pragma unroll
        for (int k = 0; k < 16; k++) acc[k] = 0.f;

        for (int j = 0; j < deg; j++) {
            int e = g_csr[start + j];
            float e0 = g_edata[(long)e * 64 + lane];
            float e1 = g_edata[(long)e * 64 + lane + 32];

            float t[N_HEADS];
            #pragma unroll
            for (int h = 0; h < N_HEADS; h++) {
                float v = e0 * aA0[h] + e1 * aA1[h];
                #pragma unroll
                for (int o = 16; o > 0; o >>= 1)
                    v += __shfl_xor_sync(0xffffffffu, v, o);
                t[h] = v;
            }
            float ex = 0.f;
            if (lane < 8) {
                float x = 0.f;
                #pragma unroll
                for (int h = 0; h < N_HEADS; h++) x += t[h] * wth[h];
                x = (x > 0.f) ? x : 0.01f * x;
                ex = __expf(x);
            }
            den += ex;
            #pragma unroll
            for (int h = 0; h < N_HEADS; h++) {
                float a = __shfl_sync(0xffffffffu, ex, h);
                acc[2*h]     += a * e0;
                acc[2*h + 1] += a * e1;
            }
        }

        float rden = (lane < 8 && den != 0.f) ? (1.0f / den) : 0.f;
        #pragma unroll
        for (int h = 0; h < N_HEADS; h++) {
            float r = __shfl_sync(0xffffffffu, rden, h);
            acc[2*h]     *= r;
            acc[2*h + 1] *= r;
        }

        float* nf = g_nodec + (long)gw * 512;
        #pragma unroll
        for (int h = 0; h < N_HEADS; h++) {
            nf[h * 64 + lane]      = acc[2*h];
            nf[h * 64 + 32 + lane] = acc[2*h + 1];
        }

        float wg0 = __ldg(Wg + lane);
        float wg1 = __ldg(Wg + lane + 32);
        float m = (float)g_mult[gw];
        #pragma unroll
        for (int h = 0; h < N_HEADS; h++) {
            float v = acc[2*h] * wg0 + acc[2*h + 1] * wg1;
            #pragma unroll
            for (int o = 16; o > 0; o >>= 1)
                v += __shfl_xor_sync(0xffffffffu, v, o);
            if (lane == 0) atomicAdd(&sG[h], m * v);
        }
    }

    __syncthreads();
    if (tid < N_HEADS) atomicAdd(&g_gate[tid], sG[tid]);
}

// =======================================================================
// K6: out = nodec[cidx[bn[b]]] * (gate[h]/B + b_gate)
// =======================================================================
extern "C" __global__ void k6_out(const int* __restrict__ bn,
                                  const float* __restrict__ bg,
                                  float* __restrict__ out, int B)
{
    long gid = (long)blockIdx.x * blockDim.x + threadIdx.x;
    if (gid >= (long)B * 128) return;
    int b = (int)(gid >> 7);
    int rem = ((int)gid & 127) << 2;
    int h = rem >> 6;
    float g = g_gate[h] * (1.0f / (float)B) + bg[0];
    int c = g_cidx[bn[b]];
    const float4 v = *(const float4*)(g_nodec + (long)c * 512 + rem);
    float4 o = make_float4(v.x * g, v.y * g, v.z * g, v.w * g);
    *(float4*)(out + (long)b * 512 + rem) = o;
}

// =======================================================================
extern "C" void kernel_launch(void* const* d_in, const int* in_sizes, int n_in,
                              void* d_out, int out_size)
{
    const int*   bn   = (const int*)  d_in[0];
    const int*   mi   = (const int*)  d_in[1];
    const int*   edst = (const int*)  d_in[2];
    const float* feat = (const float*)d_in[3];
    const float* Wi   = (const float*)d_in[4];
    const float* Wp   = (const float*)d_in[5];
    const float* attn = (const float*)d_in[6];
    const float* Wth  = (const float*)d_in[7];
    const float* Wg   = (const float*)d_in[8];
    const float* bg   = (const float*)d_in[9];

    int B = in_sizes[0];
    int E = in_sizes[2];

    void* p;
    cudaGetSymbolAddress(&p, g_gate);
    cudaMemsetAsync(p, 0, sizeof(float) * N_HEADS);
    cudaGetSymbolAddress(&p, g_flag);
    cudaMemsetAsync(p, 0, sizeof(int) * N_NODES_C);
    cudaGetSymbolAddress(&p, g_deg);
    cudaMemsetAsync(p, 0, sizeof(int) * MAX_COMP);
    cudaGetSymbolAddress(&p, g_nact);
    cudaMemsetAsync(p, 0, sizeof(int));
    cudaGetSymbolAddress(&p, g_ncomp);
    cudaMemsetAsync(p, 0, sizeof(int));
    cudaGetSymbolAddress(&p, g_total);
    cudaMemsetAsync(p, 0, sizeof(int));

    k0a_flags  <<<(B + 255) / 256, 256>>>(bn, B);
    k0b_cidx   <<<(N_NODES_C + 255) / 256, 256>>>(N_NODES_C);
    k0c_compact<<<(E + 255) / 256, 256>>>(edst, E);
    k0d_rowptr <<<(MAX_COMP + 255) / 256, 256>>>();
    k0e_fill   <<<(E + 255) / 256, 256>>>(edst);

    cudaFuncSetAttribute(k1_edata, cudaFuncAttributeMaxDynamicSharedMemorySize, K1_SMEM);
    int blocks1 = (E + K1_TILE - 1) / K1_TILE;
    k1_edata<<<blocks1, K1_THREADS, K1_SMEM>>>(mi, feat, Wi, Wp);

    long k4threads = (long)MAX_COMP * 32;
    k4_csr<<<(int)((k4threads + 255) / 256), 256>>>(attn, Wth, Wg);

    long k6threads = (long)B * 128;
    k6_out<<<(int)((k6threads + 255) / 256), 256>>>(bn, bg, (float*)d_out, B);
}